// round 1
// baseline (speedup 1.0000x reference)
#include <cuda_runtime.h>
#include <cuda_bf16.h>

// Problem constants (S=2, B=16, C=256, H=64, W=64, K=3, pad=1)
#define C_CH   256
#define H_SP   64
#define W_SP   64
#define N_IMG  (2 * 16 * C_CH)        // 8192 (n,c) images
#define SROWS  66                      // 64 rows + top/bottom halo
#define SSTRIDE 72                     // 66 cols padded; data at cols [4,68), halo at 3 and 68

__global__ __launch_bounds__(256, 2)
void dwconv3x3_kernel(const float* __restrict__ x,
                      const float* __restrict__ Wf,
                      float* __restrict__ y)
{
    __shared__ float s[SROWS * SSTRIDE];

    const int bid = blockIdx.x;            // n*C + c
    const int c   = bid & (C_CH - 1);
    const int tid = threadIdx.x;

    // Zero the whole tile (covers halo rows/cols), vectorized.
    float4* s4 = reinterpret_cast<float4*>(s);
    #pragma unroll
    for (int i = tid; i < SROWS * SSTRIDE / 4; i += 256)
        s4[i] = make_float4(0.f, 0.f, 0.f, 0.f);

    // Diagonal 3x3 filter for channel c: W[c][c][ky][kx]
    const float* wp = Wf + (size_t)c * (C_CH + 1) * 9;
    const float w00 = wp[0], w01 = wp[1], w02 = wp[2];
    const float w10 = wp[3], w11 = wp[4], w12 = wp[5];
    const float w20 = wp[6], w21 = wp[7], w22 = wp[8];

    __syncthreads();

    // Stage the 64x64 image into smem rows 1..64, cols 4..67 (16B-aligned float4 stores).
    const float* xin = x + (size_t)bid * (H_SP * W_SP);
    #pragma unroll
    for (int i = tid; i < H_SP * (W_SP / 4); i += 256) {
        const int r = i >> 4;            // row 0..63
        const int q = i & 15;            // float4 index within row
        float4 v = __ldg(reinterpret_cast<const float4*>(xin + r * W_SP + q * 4));
        *reinterpret_cast<float4*>(&s[(r + 1) * SSTRIDE + 4 + q * 4]) = v;
    }
    __syncthreads();

    float* yout = y + (size_t)bid * (H_SP * W_SP);

    // 1024 4-wide output segments; 256 threads x 4 iterations.
    #pragma unroll
    for (int it = 0; it < 4; it++) {
        const int idx = tid + it * 256;
        const int h   = idx >> 4;           // output row 0..63
        const int ws  = (idx & 15) << 2;    // output col start, multiple of 4

        // Needs smem rows h..h+2, cols ws+3..ws+8
        float a0 = 0.f, a1 = 0.f, a2 = 0.f, a3 = 0.f;

        {   // ky = 0  -> smem row h
            const float* row = &s[h * SSTRIDE + ws + 3];
            const float  v0  = row[0];
            const float4 vm  = *reinterpret_cast<const float4*>(row + 1); // aligned
            const float  v5  = row[5];
            a0 += w00 * v0   + w01 * vm.x + w02 * vm.y;
            a1 += w00 * vm.x + w01 * vm.y + w02 * vm.z;
            a2 += w00 * vm.y + w01 * vm.z + w02 * vm.w;
            a3 += w00 * vm.z + w01 * vm.w + w02 * v5;
        }
        {   // ky = 1  -> smem row h+1
            const float* row = &s[(h + 1) * SSTRIDE + ws + 3];
            const float  v0  = row[0];
            const float4 vm  = *reinterpret_cast<const float4*>(row + 1);
            const float  v5  = row[5];
            a0 += w10 * v0   + w11 * vm.x + w12 * vm.y;
            a1 += w10 * vm.x + w11 * vm.y + w12 * vm.z;
            a2 += w10 * vm.y + w11 * vm.z + w12 * vm.w;
            a3 += w10 * vm.z + w11 * vm.w + w12 * v5;
        }
        {   // ky = 2  -> smem row h+2
            const float* row = &s[(h + 2) * SSTRIDE + ws + 3];
            const float  v0  = row[0];
            const float4 vm  = *reinterpret_cast<const float4*>(row + 1);
            const float  v5  = row[5];
            a0 += w20 * v0   + w21 * vm.x + w22 * vm.y;
            a1 += w20 * vm.x + w21 * vm.y + w22 * vm.z;
            a2 += w20 * vm.y + w21 * vm.z + w22 * vm.w;
            a3 += w20 * vm.z + w21 * vm.w + w22 * v5;
        }

        float4 o = make_float4(a0, a1, a2, a3);
        *reinterpret_cast<float4*>(yout + h * W_SP + ws) = o;
    }
}

extern "C" void kernel_launch(void* const* d_in, const int* in_sizes, int n_in,
                              void* d_out, int out_size)
{
    const float* x  = (const float*)d_in[0];   // (S,B,C,H,W) fp32
    const float* Wf = (const float*)d_in[1];   // (C,C,3,3)  fp32
    float* y = (float*)d_out;

    dwconv3x3_kernel<<<N_IMG, 256>>>(x, Wf, y);
}

// round 2
// speedup vs baseline: 1.3641x; 1.3641x over previous
#include <cuda_runtime.h>
#include <cuda_bf16.h>

// Depthwise 3x3 conv, pad=1: x (2,16,256,64,64) fp32, W (256,256,3,3) -> diag only.
#define C_CH   256
#define H_SP   64
#define W_SP   64
#define N_IMG  (2 * 16 * C_CH)   // 8192 images of 64x64
#define HALF_H 32

__device__ __forceinline__ float4 f4zero() { return make_float4(0.f, 0.f, 0.f, 0.f); }

// Horizontal halo for one row: l = previous lane's .w, r = next lane's .x,
// zeroed at the 16-lane group boundaries (each 16-lane group is an independent strip).
__device__ __forceinline__ void halo(const float4& v, int lane16, float& l, float& r)
{
    l = __shfl_up_sync(0xffffffffu, v.w, 1);
    r = __shfl_down_sync(0xffffffffu, v.x, 1);
    if (lane16 == 0)  l = 0.f;
    if (lane16 == 15) r = 0.f;
}

__global__ __launch_bounds__(256)
void dwconv3x3_reg_kernel(const float* __restrict__ x,
                          const float* __restrict__ Wf,
                          float* __restrict__ y)
{
    const int tid    = threadIdx.x;
    const int warp   = tid >> 5;
    const int lane   = tid & 31;
    const int lane16 = lane & 15;

    // One warp = one image. Lanes 0-15: rows [0,32). Lanes 16-31: rows [32,64).
    const int image = blockIdx.x * 8 + warp;            // 0..8191
    const int c     = image & (C_CH - 1);
    const int top   = (lane >> 4) * HALF_H;             // 0 or 32
    const int col   = lane16 << 2;                      // 0,4,...,60

    // Diagonal filter W[c][c][ky][kx] — warp-uniform.
    const float* wp = Wf + (size_t)c * (C_CH + 1) * 9;
    const float w00 = __ldg(wp + 0), w01 = __ldg(wp + 1), w02 = __ldg(wp + 2);
    const float w10 = __ldg(wp + 3), w11 = __ldg(wp + 4), w12 = __ldg(wp + 5);
    const float w20 = __ldg(wp + 6), w21 = __ldg(wp + 7), w22 = __ldg(wp + 8);

    const float* xin  = x + (size_t)image * (H_SP * W_SP) + col;
    float*       yout = y + (size_t)image * (H_SP * W_SP) + col;

    // Register sliding window: rows (m)inus, (c)enter, (n)ext + their halos.
    float4 vm, vc, vn;
    float  lm, rm, lc, rc_, ln, rn;

    // Preload rows top-1, top, top+1 (top+1 <= 33 always valid; top-1 < 0 -> zero).
    vm = (top - 1 >= 0) ? __ldg((const float4*)(xin + (top - 1) * W_SP)) : f4zero();
    vc = __ldg((const float4*)(xin + top * W_SP));
    vn = __ldg((const float4*)(xin + (top + 1) * W_SP));
    halo(vm, lane16, lm, rm);
    halo(vc, lane16, lc, rc_);
    halo(vn, lane16, ln, rn);

    #pragma unroll 8
    for (int r = 0; r < HALF_H; r++) {
        // Prefetch row top+r+2 (zero past the image bottom).
        const int gpre = top + r + 2;
        float4 vp = (gpre < H_SP) ? __ldg((const float4*)(xin + gpre * W_SP)) : f4zero();
        float lp, rp;
        halo(vp, lane16, lp, rp);

        // Compute output row top+r.
        float4 o;
        o.x = w00*lm   + w01*vm.x + w02*vm.y
            + w10*lc   + w11*vc.x + w12*vc.y
            + w20*ln   + w21*vn.x + w22*vn.y;
        o.y = w00*vm.x + w01*vm.y + w02*vm.z
            + w10*vc.x + w11*vc.y + w12*vc.z
            + w20*vn.x + w21*vn.y + w22*vn.z;
        o.z = w00*vm.y + w01*vm.z + w02*vm.w
            + w10*vc.y + w11*vc.z + w12*vc.w
            + w20*vn.y + w21*vn.z + w22*vn.w;
        o.w = w00*vm.z + w01*vm.w + w02*rm
            + w10*vc.z + w11*vc.w + w12*rc_
            + w20*vn.z + w21*vn.w + w22*rn;

        *(float4*)(yout + (top + r) * W_SP) = o;

        // Slide the window.
        vm = vc; lm = lc; rm = rc_;
        vc = vn; lc = ln; rc_ = rn;
        vn = vp; ln = lp; rn = rp;
    }
}

extern "C" void kernel_launch(void* const* d_in, const int* in_sizes, int n_in,
                              void* d_out, int out_size)
{
    const float* x  = (const float*)d_in[0];   // (S,B,C,H,W) fp32
    const float* Wf = (const float*)d_in[1];   // (C,C,3,3)  fp32
    float* y = (float*)d_out;

    dwconv3x3_reg_kernel<<<N_IMG / 8, 256>>>(x, Wf, y);
}